// round 2
// baseline (speedup 1.0000x reference)
#include <cuda_runtime.h>
#include <stdint.h>

// VQ-VAE quantization with bit-faithful emulation of the reference's fp32
// distance computation:
//   znorm_p = sequential fp32 sum of z_p[d]^2          (matches XLA CPU reduce)
//   enorm_k = sequential fp32 sum of e_k[d]^2
//   dist    = rn( rn(znorm + enorm) - 2*dot )          (2*dot exact in fp32)
//   idx     = argmin(dist), ties -> smallest k          (jnp.argmin)
//   out0    = rn( z + rn(code - z) )  (straight-through value, fp32-rounded)
//   out1    = x
//   out2    = code
// dot is computed with FMA in any order: its |error| ~1e-8 << ulp(dist) ~3e-5,
// so the reference's quantized tie structure is preserved.

#define BATCH 64
#define DIM   256
#define KCB   512
#define HWSZ  1024
#define POS   32
#define SEC   ((size_t)BATCH * DIM * HWSZ)

__device__ float d_enorm[KCB];

__global__ void enorm_kernel(const float* __restrict__ emb) {
    int k = blockIdx.x * blockDim.x + threadIdx.x;
    if (k < KCB) {
        const float* e = emb + (size_t)k * DIM;
        float acc = 0.f;
        for (int d = 0; d < DIM; ++d)           // sequential, no FMA
            acc = __fadd_rn(acc, __fmul_rn(e[d], e[d]));
        d_enorm[k] = acc;
    }
}

__device__ __forceinline__ unsigned int ordkey(float f) {
    unsigned int u = __float_as_uint(f);
    return (u & 0x80000000u) ? ~u : (u | 0x80000000u);   // monotonic: min key = min float
}

__global__ __launch_bounds__(256) void vq_kernel(const float* __restrict__ x,
                                                 const float* __restrict__ emb,
                                                 float* __restrict__ out) {
    __shared__ float xs[DIM][POS];                 // 32 KB x tile, d-major
    __shared__ float zn[POS];
    __shared__ unsigned long long red[POS][33];
    __shared__ int idx_s[POS];

    const int b    = blockIdx.x >> 5;
    const int tile = blockIdx.x & 31;
    const int p0   = tile * POS;
    const int t    = threadIdx.x;
    const int w    = t >> 5;
    const int lane = t & 31;

    // ---- stage x tile (coalesced 128B rows) ----
    const float* gx = x + (size_t)b * DIM * HWSZ + p0;
    #pragma unroll 4
    for (int r = 0; r < 32; ++r) {
        int d = w * 32 + r;
        xs[d][lane] = gx[(size_t)d * HWSZ + lane];
    }
    __syncthreads();

    // ---- znorm: strictly sequential fp32 chain per position ----
    if (t < POS) {
        float acc = 0.f;
        #pragma unroll 8
        for (int d = 0; d < DIM; ++d)
            acc = __fadd_rn(acc, __fmul_rn(xs[d][t], xs[d][t]));
        zn[t] = acc;
    }
    __syncthreads();

    // ---- dot products: 2 codes x 4 positions per thread ----
    const int pg = t & 7;
    const int kg = t >> 3;
    const int pt = pg * 4;

    unsigned long long best[4] = {~0ull, ~0ull, ~0ull, ~0ull};
    float znr[4];
    #pragma unroll
    for (int c = 0; c < 4; ++c) znr[c] = zn[pt + c];

    for (int j = 0; j < 8; ++j) {
        const int k0 = kg * 2 + j * 64;
        float acc0[4] = {0.f, 0.f, 0.f, 0.f};
        float acc1[4] = {0.f, 0.f, 0.f, 0.f};
        const float4* e0 = (const float4*)(emb + (size_t)k0 * DIM);
        const float4* e1 = (const float4*)(emb + (size_t)(k0 + 1) * DIM);

        #pragma unroll 4
        for (int d4 = 0; d4 < DIM / 4; ++d4) {
            float4 ea = e0[d4];
            float4 eb = e1[d4];
            const int d = d4 * 4;
            float xv[4][4];
            *(float4*)xv[0] = *(const float4*)&xs[d + 0][pt];
            *(float4*)xv[1] = *(const float4*)&xs[d + 1][pt];
            *(float4*)xv[2] = *(const float4*)&xs[d + 2][pt];
            *(float4*)xv[3] = *(const float4*)&xs[d + 3][pt];
            const float* pea = (const float*)&ea;
            const float* peb = (const float*)&eb;
            #pragma unroll
            for (int dd = 0; dd < 4; ++dd) {
                float e_a = pea[dd];
                float e_b = peb[dd];
                #pragma unroll
                for (int c = 0; c < 4; ++c) {
                    acc0[c] += e_a * xv[dd][c];
                    acc1[c] += e_b * xv[dd][c];
                }
            }
        }

        const float en0 = d_enorm[k0];
        const float en1 = d_enorm[k0 + 1];
        #pragma unroll
        for (int c = 0; c < 4; ++c) {
            float t1   = __fadd_rn(znr[c], en0);
            float dist = __fadd_rn(t1, __fmul_rn(-2.0f, acc0[c]));
            unsigned long long key0 =
                ((unsigned long long)ordkey(dist) << 32) | (unsigned)k0;
            float t2    = __fadd_rn(znr[c], en1);
            float dist1 = __fadd_rn(t2, __fmul_rn(-2.0f, acc1[c]));
            unsigned long long key1 =
                ((unsigned long long)ordkey(dist1) << 32) | (unsigned)(k0 + 1);
            if (key0 < best[c]) best[c] = key0;
            if (key1 < best[c]) best[c] = key1;
        }
    }

    #pragma unroll
    for (int c = 0; c < 4; ++c) red[pt + c][kg] = best[c];
    __syncthreads();

    // ---- per-position argmin over the 32 code groups (ties -> smallest k) ----
    if (t < POS) {
        unsigned long long m = ~0ull;
        #pragma unroll 8
        for (int i = 0; i < 32; ++i) {
            unsigned long long v = red[t][i];
            if (v < m) m = v;
        }
        idx_s[t] = (int)(m & 0xFFFFFFFFull);
    }
    __syncthreads();

    // ---- write outputs ----
    const int kq = idx_s[lane];
    const size_t obase = (size_t)b * DIM * HWSZ + p0 + lane;
    #pragma unroll 4
    for (int d = w; d < DIM; d += 8) {
        float v = __ldg(&emb[(size_t)kq * DIM + d]);
        float z = xs[d][lane];
        size_t off = obase + (size_t)d * HWSZ;
        // straight-through value with the reference's exact fp32 rounding
        out[off]           = __fadd_rn(z, __fadd_rn(v, -z));
        out[off + SEC]     = z;           // x passthrough
        out[off + 2 * SEC] = v;           // z_q_bar = gathered code
    }
}

extern "C" void kernel_launch(void* const* d_in, const int* in_sizes, int n_in,
                              void* d_out, int out_size) {
    const float* x   = (const float*)d_in[0];
    const float* emb = (const float*)d_in[1];
    float* out = (float*)d_out;
    (void)in_sizes; (void)n_in; (void)out_size;

    enorm_kernel<<<1, 512>>>(emb);
    vq_kernel<<<BATCH * (HWSZ / POS), 256>>>(x, emb, out);
}

// round 3
// speedup vs baseline: 1.3007x; 1.3007x over previous
#include <cuda_runtime.h>
#include <stdint.h>

// VQ-VAE quantization, bit-faithful argmin (validated rel_err==0.0 in R2).
// R3: 8 pos x 8 code register tile per thread -> 0.75 B l1tex traffic per FMA
// (was 3 B/FMA, l1tex 87% bound). Per-(p,k) FMA chain stays strictly
// sequential over d=0..255 => identical bits to the R2-validated kernel.

#define BATCH 64
#define DIM   256
#define KCB   512
#define HWSZ  1024
#define POS   32
#define SEC   ((size_t)BATCH * DIM * HWSZ)

__device__ float d_enorm[KCB];

__global__ void enorm_kernel(const float* __restrict__ emb) {
    int k = blockIdx.x * blockDim.x + threadIdx.x;
    if (k < KCB) {
        const float* e = emb + (size_t)k * DIM;
        float acc = 0.f;
        for (int d = 0; d < DIM; ++d)              // sequential, no FMA
            acc = __fadd_rn(acc, __fmul_rn(e[d], e[d]));
        d_enorm[k] = acc;
    }
}

__device__ __forceinline__ unsigned int ordkey(float f) {
    unsigned int u = __float_as_uint(f);
    return (u & 0x80000000u) ? ~u : (u | 0x80000000u);
}

__global__ __launch_bounds__(256, 2) void vq_kernel(const float* __restrict__ x,
                                                    const float* __restrict__ emb,
                                                    float* __restrict__ out) {
    __shared__ float xs[DIM][POS];                 // 32 KB x tile, d-major
    __shared__ float zn[POS];
    __shared__ unsigned long long red[POS][9];     // [pos][warp]
    __shared__ int idx_s[POS];

    const int b    = blockIdx.x >> 5;
    const int tile = blockIdx.x & 31;
    const int p0   = tile * POS;
    const int t    = threadIdx.x;
    const int w    = t >> 5;
    const int lane = t & 31;

    // ---- stage x tile (coalesced 128B rows) ----
    const float* gx = x + (size_t)b * DIM * HWSZ + p0;
    #pragma unroll 4
    for (int r = 0; r < 32; ++r) {
        int d = w * 32 + r;
        xs[d][lane] = gx[(size_t)d * HWSZ + lane];
    }
    __syncthreads();

    // ---- znorm: strictly sequential fp32 chain per position ----
    if (t < POS) {
        float acc = 0.f;
        #pragma unroll 8
        for (int d = 0; d < DIM; ++d)
            acc = __fadd_rn(acc, __fmul_rn(xs[d][t], xs[d][t]));
        zn[t] = acc;
    }
    __syncthreads();

    // ---- 8 pos x 8 code register tile ----
    const int pg = t & 3;          // pos group 0..3  -> positions pg*8 .. pg*8+7
    const int cg = t >> 2;         // code group 0..63 -> codes cg*8 .. cg*8+7
    const int pt = pg * 8;
    const int k0 = cg * 8;

    float acc[8][8];               // [code i][pos c]
    #pragma unroll
    for (int i = 0; i < 8; ++i)
        #pragma unroll
        for (int c = 0; c < 8; ++c) acc[i][c] = 0.f;

    const float2* ep = (const float2*)(emb + (size_t)k0 * DIM);

    #pragma unroll 2
    for (int d2 = 0; d2 < DIM / 2; ++d2) {
        float2 ev[8];
        #pragma unroll
        for (int i = 0; i < 8; ++i) ev[i] = ep[d2 + i * (DIM / 2)];

        #pragma unroll
        for (int dd = 0; dd < 2; ++dd) {
            const int d = 2 * d2 + dd;
            float xv[8];
            *(float4*)&xv[0] = *(const float4*)&xs[d][pt];
            *(float4*)&xv[4] = *(const float4*)&xs[d][pt + 4];
            #pragma unroll
            for (int i = 0; i < 8; ++i) {
                const float e = dd ? ev[i].y : ev[i].x;
                #pragma unroll
                for (int c = 0; c < 8; ++c)
                    acc[i][c] = fmaf(e, xv[c], acc[i][c]);   // sequential in d per (p,k)
            }
        }
    }

    // ---- per-thread keys, then warp bfly-reduce over code groups ----
    unsigned long long key[8];
    float en[8];
    #pragma unroll
    for (int i = 0; i < 8; ++i) en[i] = d_enorm[k0 + i];

    #pragma unroll
    for (int c = 0; c < 8; ++c) {
        const float z = zn[pt + c];
        unsigned long long m = ~0ull;
        #pragma unroll
        for (int i = 0; i < 8; ++i) {
            float dist = __fadd_rn(__fadd_rn(z, en[i]), __fmul_rn(-2.0f, acc[i][c]));
            unsigned long long kk =
                ((unsigned long long)ordkey(dist) << 32) | (unsigned)(k0 + i);
            if (kk < m) m = kk;
        }
        key[c] = m;
    }

    // lanes with the same pg sit at stride 4: reduce over xor 4, 8, 16
    #pragma unroll
    for (int msk = 4; msk <= 16; msk <<= 1) {
        #pragma unroll
        for (int c = 0; c < 8; ++c) {
            unsigned long long o = __shfl_xor_sync(0xFFFFFFFFu, key[c], msk);
            if (o < key[c]) key[c] = o;
        }
    }
    if ((lane & 28) == 0) {        // one lane per pos-group per warp
        #pragma unroll
        for (int c = 0; c < 8; ++c) red[pt + c][w] = key[c];
    }
    __syncthreads();

    if (t < POS) {
        unsigned long long m = ~0ull;
        #pragma unroll
        for (int i = 0; i < 8; ++i) {
            unsigned long long v = red[t][i];
            if (v < m) m = v;
        }
        idx_s[t] = (int)(m & 0xFFFFFFFFull);
    }
    __syncthreads();

    // ---- write outputs (coalesced 128B rows) ----
    const int kq = idx_s[lane];
    const size_t obase = (size_t)b * DIM * HWSZ + p0 + lane;
    #pragma unroll 4
    for (int d = w; d < DIM; d += 8) {
        float v = __ldg(&emb[(size_t)kq * DIM + d]);
        float z = xs[d][lane];
        size_t off = obase + (size_t)d * HWSZ;
        out[off]           = __fadd_rn(z, __fadd_rn(v, -z));  // straight-through value
        out[off + SEC]     = z;                               // x passthrough
        out[off + 2 * SEC] = v;                               // gathered code
    }
}

extern "C" void kernel_launch(void* const* d_in, const int* in_sizes, int n_in,
                              void* d_out, int out_size) {
    const float* x   = (const float*)d_in[0];
    const float* emb = (const float*)d_in[1];
    float* out = (float*)d_out;
    (void)in_sizes; (void)n_in; (void)out_size;

    enorm_kernel<<<8, 64>>>(emb);
    vq_kernel<<<BATCH * (HWSZ / POS), 256>>>(x, emb, out);
}

// round 4
// speedup vs baseline: 1.5619x; 1.2008x over previous
#include <cuda_runtime.h>
#include <stdint.h>

// VQ-VAE quantization, bit-faithful argmin (rel_err==0.0 validated R2/R3).
// R4: (a) emb staged to smem transposed [d][k] per 16-d chunk -> e-reads are
// conflict-free LDS.128 (was 8-row-scattered LDG.64, ~8 wavefronts each,
// l1tex 90% bound). (b) packed fp32 FMA (fma.rn.f32x2 -> FFMA2) pairing two
// POSITIONS per instruction: each element keeps its strictly-sequential
// per-(p,k) fp32 rn chain over d => bitwise-identical dist to R2.

#define BATCH 64
#define DIM   256
#define KCB   512
#define HWSZ  1024
#define POS   32
#define DC    16                 // d-chunk staged per iteration
#define SEC   ((size_t)BATCH * DIM * HWSZ)

#define ES_PAD 516               // padded row to reduce STS bank conflicts

__device__ float d_enorm[KCB];

__global__ void enorm_kernel(const float* __restrict__ emb) {
    int k = blockIdx.x * blockDim.x + threadIdx.x;
    if (k < KCB) {
        const float* e = emb + (size_t)k * DIM;
        float acc = 0.f;
        for (int d = 0; d < DIM; ++d)
            acc = __fadd_rn(acc, __fmul_rn(e[d], e[d]));
        d_enorm[k] = acc;
    }
}

__device__ __forceinline__ unsigned int ordkey(float f) {
    unsigned int u = __float_as_uint(f);
    return (u & 0x80000000u) ? ~u : (u | 0x80000000u);
}

__device__ __forceinline__ unsigned long long bcast2(float a) {
    unsigned long long r;
    asm("mov.b64 %0, {%1, %1};" : "=l"(r) : "f"(a));
    return r;
}
__device__ __forceinline__ unsigned long long fma2(unsigned long long a,
                                                   unsigned long long b,
                                                   unsigned long long c) {
    unsigned long long d;
    asm("fma.rn.f32x2 %0, %1, %2, %3;" : "=l"(d) : "l"(a), "l"(b), "l"(c));
    return d;
}
__device__ __forceinline__ void unpack2(unsigned long long v, float& lo, float& hi) {
    asm("mov.b64 {%0, %1}, %2;" : "=f"(lo), "=f"(hi) : "l"(v));
}

__global__ __launch_bounds__(256, 2) void vq_kernel(const float* __restrict__ x,
                                                    const float* __restrict__ emb,
                                                    float* __restrict__ out) {
    extern __shared__ float smem[];
    float (*xs)[POS]    = (float (*)[POS])smem;               // [256][32] 32 KB
    float (*es)[ES_PAD] = (float (*)[ES_PAD])(smem + DIM * POS); // [16][516] 33 KB

    __shared__ unsigned long long red[POS][9];
    __shared__ float zn[POS];
    __shared__ int idx_s[POS];

    const int b    = blockIdx.x >> 5;
    const int tile = blockIdx.x & 31;
    const int p0   = tile * POS;
    const int t    = threadIdx.x;
    const int w    = t >> 5;
    const int lane = t & 31;

    // ---- stage x tile (coalesced 128B rows) ----
    const float* gx = x + (size_t)b * DIM * HWSZ + p0;
    #pragma unroll 4
    for (int r = 0; r < 32; ++r) {
        int d = w * 32 + r;
        xs[d][lane] = gx[(size_t)d * HWSZ + lane];
    }
    __syncthreads();

    // ---- znorm: strictly sequential fp32 chain per position ----
    if (t < POS) {
        float acc = 0.f;
        #pragma unroll 8
        for (int d = 0; d < DIM; ++d)
            acc = __fadd_rn(acc, __fmul_rn(xs[d][t], xs[d][t]));
        zn[t] = acc;
    }

    // ---- 8 pos x 8 code tile; positions paired into f32x2 lanes ----
    const int pg = t & 3;          // pos group: positions pg*8 .. pg*8+7
    const int cg = t >> 2;         // code group: codes cg*8 .. cg*8+7
    const int pt = pg * 8;
    const int k0 = cg * 8;

    unsigned long long acc2[8][4];          // [code][pos-pair]
    #pragma unroll
    for (int i = 0; i < 8; ++i)
        #pragma unroll
        for (int c = 0; c < 4; ++c) acc2[i][c] = 0ull;

    const int srow = t >> 2;       // staging row base (0..63)
    const int dcol = (t & 3) * 4;  // staging d columns

    for (int cc = 0; cc < DIM / DC; ++cc) {
        const int d0 = cc * DC;
        __syncthreads();
        // stage es[dd][k] = emb[k][d0+dd], coalesced float4 reads
        #pragma unroll
        for (int pass = 0; pass < 8; ++pass) {
            int row = srow + pass * 64;
            float4 v = *(const float4*)&emb[(size_t)row * DIM + d0 + dcol];
            es[dcol + 0][row] = v.x;
            es[dcol + 1][row] = v.y;
            es[dcol + 2][row] = v.z;
            es[dcol + 3][row] = v.w;
        }
        __syncthreads();

        #pragma unroll 4
        for (int dd = 0; dd < DC; ++dd) {
            const int d = d0 + dd;
            const ulonglong2* xrow = (const ulonglong2*)&xs[d][pt];
            ulonglong2 xa = xrow[0];
            ulonglong2 xb = xrow[1];
            unsigned long long xp[4] = {xa.x, xa.y, xb.x, xb.y};
            float4 e0 = *(const float4*)&es[dd][k0];
            float4 e1 = *(const float4*)&es[dd][k0 + 4];
            const float ev[8] = {e0.x, e0.y, e0.z, e0.w, e1.x, e1.y, e1.z, e1.w};
            #pragma unroll
            for (int i = 0; i < 8; ++i) {
                unsigned long long eb = bcast2(ev[i]);
                #pragma unroll
                for (int c = 0; c < 4; ++c)
                    acc2[i][c] = fma2(eb, xp[c], acc2[i][c]);
            }
        }
    }

    // ---- keys + reductions (identical math to validated kernel) ----
    float en[8];
    #pragma unroll
    for (int i = 0; i < 8; ++i) en[i] = d_enorm[k0 + i];

    unsigned long long key[8];
    #pragma unroll
    for (int c2 = 0; c2 < 4; ++c2) {
        float dot_lo[8], dot_hi[8];
        #pragma unroll
        for (int i = 0; i < 8; ++i) unpack2(acc2[i][c2], dot_lo[i], dot_hi[i]);

        const float z_lo = zn[pt + 2 * c2];
        const float z_hi = zn[pt + 2 * c2 + 1];
        unsigned long long m_lo = ~0ull, m_hi = ~0ull;
        #pragma unroll
        for (int i = 0; i < 8; ++i) {
            float dl = __fadd_rn(__fadd_rn(z_lo, en[i]), __fmul_rn(-2.0f, dot_lo[i]));
            float dh = __fadd_rn(__fadd_rn(z_hi, en[i]), __fmul_rn(-2.0f, dot_hi[i]));
            unsigned long long kl = ((unsigned long long)ordkey(dl) << 32) | (unsigned)(k0 + i);
            unsigned long long kh = ((unsigned long long)ordkey(dh) << 32) | (unsigned)(k0 + i);
            if (kl < m_lo) m_lo = kl;
            if (kh < m_hi) m_hi = kh;
        }
        key[2 * c2]     = m_lo;
        key[2 * c2 + 1] = m_hi;
    }

    // warp bfly-reduce over code groups (same pg at lane stride 4)
    #pragma unroll
    for (int msk = 4; msk <= 16; msk <<= 1) {
        #pragma unroll
        for (int c = 0; c < 8; ++c) {
            unsigned long long o = __shfl_xor_sync(0xFFFFFFFFu, key[c], msk);
            if (o < key[c]) key[c] = o;
        }
    }
    if ((lane & 28) == 0) {
        #pragma unroll
        for (int c = 0; c < 8; ++c) red[pt + c][w] = key[c];
    }
    __syncthreads();

    if (t < POS) {
        unsigned long long m = ~0ull;
        #pragma unroll
        for (int i = 0; i < 8; ++i) {
            unsigned long long v = red[t][i];
            if (v < m) m = v;
        }
        idx_s[t] = (int)(m & 0xFFFFFFFFull);
    }
    __syncthreads();

    // ---- write outputs (coalesced 128B rows) ----
    const int kq = idx_s[lane];
    const size_t obase = (size_t)b * DIM * HWSZ + p0 + lane;
    #pragma unroll 4
    for (int d = w; d < DIM; d += 8) {
        float v = __ldg(&emb[(size_t)kq * DIM + d]);
        float z = xs[d][lane];
        size_t off = obase + (size_t)d * HWSZ;
        out[off]           = __fadd_rn(z, __fadd_rn(v, -z));
        out[off + SEC]     = z;
        out[off + 2 * SEC] = v;
    }
}

extern "C" void kernel_launch(void* const* d_in, const int* in_sizes, int n_in,
                              void* d_out, int out_size) {
    const float* x   = (const float*)d_in[0];
    const float* emb = (const float*)d_in[1];
    float* out = (float*)d_out;
    (void)in_sizes; (void)n_in; (void)out_size;

    static int smem_set = 0;
    const int dyn_smem = (DIM * POS + DC * ES_PAD) * (int)sizeof(float);  // ~65 KB
    if (!smem_set) {
        cudaFuncSetAttribute(vq_kernel, cudaFuncAttributeMaxDynamicSharedMemorySize,
                             dyn_smem);
        smem_set = 1;
    }

    enorm_kernel<<<8, 64>>>(emb);
    vq_kernel<<<BATCH * (HWSZ / POS), 256, dyn_smem>>>(x, emb, out);
}